// round 4
// baseline (speedup 1.0000x reference)
#include <cuda_runtime.h>

#define N_MAX 100000
#define E_MAX 1200000
#define DIN   64
#define DHID  64
#define DOUT  34
#define SCAN_BS 512
#define NB_MAX ((N_MAX + SCAN_BS - 1) / SCAN_BS)

// ---- scratch (allocation-free: __device__ globals) ----
__device__ int   g_deg [N_MAX];
__device__ float g_dinv[N_MAX];
__device__ int   g_off [N_MAX + 1];       // CSR offsets (real in-edges per dst)
__device__ int   g_cur [N_MAX];           // fill cursors
__device__ int   g_bsum[NB_MAX];          // scan block sums
__device__ int2  g_edge[E_MAX];           // CSR: (src, bits(dinv[src])) per edge
__device__ float g_s   [(size_t)N_MAX * DIN];   // pre-aggregated + self input
__device__ float g_hw  [(size_t)N_MAX * DOUT];  // softmax(relu(h)) @ W2

// ---------------------------------------------------------------------------
__global__ void k_deg_count(const int* __restrict__ dst, int e) {
    int i = blockIdx.x * blockDim.x + threadIdx.x;
    if (i < e) atomicAdd(&g_deg[dst[i]], 1);
}

// ---- per-segment exclusive scan of deg (real in-edges); also dinv --------
__global__ void k_scan1(int n) {
    __shared__ int sh[SCAN_BS];
    int i = blockIdx.x * SCAN_BS + threadIdx.x;
    int v = (i < n) ? g_deg[i] : 0;
    if (i < n) g_dinv[i] = rsqrtf((float)(v + 1));   // +1 self-loop
    sh[threadIdx.x] = v;
    __syncthreads();
    for (int off = 1; off < SCAN_BS; off <<= 1) {
        int t = (threadIdx.x >= off) ? sh[threadIdx.x - off] : 0;
        __syncthreads();
        sh[threadIdx.x] += t;
        __syncthreads();
    }
    if (i < n) g_off[i] = sh[threadIdx.x] - v;
    if (threadIdx.x == SCAN_BS - 1) g_bsum[blockIdx.x] = sh[threadIdx.x];
}

// ---- finalize offsets: each block self-computes its segment prefix -------
__global__ void k_scan3(int nb, int n) {
    __shared__ int red[SCAN_BS / 32];
    __shared__ int pref;
    int sb = blockIdx.x, t = threadIdx.x;

    int v = (t < sb) ? g_bsum[t] : 0;
#pragma unroll
    for (int o = 16; o; o >>= 1) v += __shfl_xor_sync(0xffffffffu, v, o);
    if ((t & 31) == 0) red[t >> 5] = v;
    __syncthreads();
    if (t < 32) {
        int vv = (t < SCAN_BS / 32) ? red[t] : 0;
#pragma unroll
        for (int o = 16; o; o >>= 1) vv += __shfl_xor_sync(0xffffffffu, vv, o);
        if (t == 0) pref = vv;
    }
    __syncthreads();
    int prefix = pref;

    int i = sb * SCAN_BS + t;
    if (i < n) {
        int o = g_off[i] + prefix;
        g_off[i] = o;
        g_cur[i] = o;
    }
    if (sb == nb - 1 && t == 0) g_off[n] = prefix + g_bsum[sb];
}

__global__ void k_fill(const int* __restrict__ src, const int* __restrict__ dst, int e) {
    int i = blockIdx.x * blockDim.x + threadIdx.x;
    if (i < e) {
        int s = src[i];
        int pos = atomicAdd(&g_cur[dst[i]], 1);
        g_edge[pos] = make_int2(s, __float_as_int(g_dinv[s]));
    }
}

// ---------------------------------------------------------------------------
// Pre-GEMM aggregation: g_s[i] = dinv[i]*(sum_e dinv[src]*x[src] + dinv[i]*x[i])
// Warp per node; 2 half-warp edge streams x unroll-4 -> 8 gathers in flight.
__global__ void k_aggx(const float* __restrict__ x, int n) {
    int warp = threadIdx.x >> 5, lane = threadIdx.x & 31;
    int node = blockIdx.x * 8 + warp;
    if (node >= n) return;
    int beg = g_off[node], end = g_off[node + 1];
    int half = lane >> 4, sub = lane & 15;

    float4 acc = make_float4(0.f, 0.f, 0.f, 0.f);
    for (int j = beg; j < end; j += 32) {
        int idx = j + lane;
        int2 ed = make_int2(0, 0);
        if (idx < end) ed = __ldg(&g_edge[idx]);
        int m  = min(32, end - j);
        int mt = (m + 1) >> 1;       // warp-uniform trips per half-stream
        int t  = 0;
        for (; t + 4 <= mt; t += 4) {
#pragma unroll
            for (int u = 0; u < 4; u++) {
                int l = 2 * (t + u) + half;
                int   s = __shfl_sync(0xffffffffu, ed.x, l);
                float w = __int_as_float(__shfl_sync(0xffffffffu, ed.y, l));
                if (l < m) {
                    float4 v = __ldg((const float4*)(x + (size_t)s * DIN + sub * 4));
                    acc.x = fmaf(w, v.x, acc.x); acc.y = fmaf(w, v.y, acc.y);
                    acc.z = fmaf(w, v.z, acc.z); acc.w = fmaf(w, v.w, acc.w);
                }
            }
        }
        for (; t < mt; t++) {
            int l = 2 * t + half;
            int   s = __shfl_sync(0xffffffffu, ed.x, l);
            float w = __int_as_float(__shfl_sync(0xffffffffu, ed.y, l));
            if (l < m) {
                float4 v = __ldg((const float4*)(x + (size_t)s * DIN + sub * 4));
                acc.x = fmaf(w, v.x, acc.x); acc.y = fmaf(w, v.y, acc.y);
                acc.z = fmaf(w, v.z, acc.z); acc.w = fmaf(w, v.w, acc.w);
            }
        }
    }
    acc.x += __shfl_xor_sync(0xffffffffu, acc.x, 16);
    acc.y += __shfl_xor_sync(0xffffffffu, acc.y, 16);
    acc.z += __shfl_xor_sync(0xffffffffu, acc.z, 16);
    acc.w += __shfl_xor_sync(0xffffffffu, acc.w, 16);
    if (half == 0) {
        float dn = g_dinv[node];
        float4 xv = __ldg((const float4*)(x + (size_t)node * DIN + sub * 4));
        float4 s;
        s.x = dn * fmaf(dn, xv.x, acc.x);
        s.y = dn * fmaf(dn, xv.y, acc.y);
        s.z = dn * fmaf(dn, xv.z, acc.z);
        s.w = dn * fmaf(dn, xv.w, acc.w);
        *(float4*)(g_s + (size_t)node * DIN + sub * 4) = s;
    }
}

// ---------------------------------------------------------------------------
// Fused: h = g_s @ W1 + b1 ; p = softmax(relu(h)) ; hw = p @ W2 ;
// out init = b2 + dinv^2 * hw. Warp handles 4 rows; paired-k inner loops.
__global__ void k_fused(const float* __restrict__ W1, const float* __restrict__ b1,
                        const float* __restrict__ W2, const float* __restrict__ b2,
                        float* __restrict__ out, int n) {
    __shared__ float W1s[DIN * DHID];       // 16 KB
    __shared__ float W2s[DHID * DOUT];      // 8.5 KB
    __shared__ float buf[8][4][DHID];       // 8 KB: xs then ps
    for (int i = threadIdx.x; i < DIN * DHID; i += blockDim.x)  W1s[i] = W1[i];
    for (int i = threadIdx.x; i < DHID * DOUT; i += blockDim.x) W2s[i] = W2[i];
    __syncthreads();

    int warp = threadIdx.x >> 5, lane = threadIdx.x & 31;
    int row0 = blockIdx.x * 32 + warp * 4;

#pragma unroll
    for (int r = 0; r < 4; r++) {
        int row = row0 + r;
        float2 xv = make_float2(0.f, 0.f);
        if (row < n) xv = *(const float2*)(g_s + (size_t)row * DIN + lane * 2);
        buf[warp][r][lane * 2]     = xv.x;
        buf[warp][r][lane * 2 + 1] = xv.y;
    }
    __syncwarp();

    float2 a[4];
#pragma unroll
    for (int r = 0; r < 4; r++) a[r] = make_float2(0.f, 0.f);
#pragma unroll
    for (int k = 0; k < DIN; k += 2) {
        float2 w0 = *(const float2*)(W1s + k * DHID + lane * 2);
        float2 w1 = *(const float2*)(W1s + (k + 1) * DHID + lane * 2);
#pragma unroll
        for (int r = 0; r < 4; r++) {
            float2 xk = *(const float2*)(&buf[warp][r][k]);
            a[r].x = fmaf(xk.x, w0.x, a[r].x);
            a[r].y = fmaf(xk.x, w0.y, a[r].y);
            a[r].x = fmaf(xk.y, w1.x, a[r].x);
            a[r].y = fmaf(xk.y, w1.y, a[r].y);
        }
    }
    __syncwarp();

    float2 bb = *(const float2*)(b1 + lane * 2);
#pragma unroll
    for (int r = 0; r < 4; r++) {
        float v0 = fmaxf(a[r].x + bb.x, 0.f);
        float v1 = fmaxf(a[r].y + bb.y, 0.f);
        float m = fmaxf(v0, v1);
#pragma unroll
        for (int off = 16; off; off >>= 1)
            m = fmaxf(m, __shfl_xor_sync(0xffffffffu, m, off));
        float e0 = __expf(v0 - m), e1 = __expf(v1 - m);
        float ssum = e0 + e1;
#pragma unroll
        for (int off = 16; off; off >>= 1)
            ssum += __shfl_xor_sync(0xffffffffu, ssum, off);
        float inv = 1.0f / ssum;
        buf[warp][r][lane * 2]     = e0 * inv;
        buf[warp][r][lane * 2 + 1] = e1 * inv;
    }
    __syncwarp();

    int  c2   = lane + 32;
    bool has2 = (c2 < DOUT);
    int  c2c  = has2 ? c2 : (DOUT - 1);
    float a0[4] = {0.f, 0.f, 0.f, 0.f};
    float a1[4] = {0.f, 0.f, 0.f, 0.f};
#pragma unroll
    for (int k = 0; k < DHID; k += 2) {
        float w00 = W2s[k * DOUT + lane];
        float w01 = W2s[k * DOUT + c2c];
        float w10 = W2s[(k + 1) * DOUT + lane];
        float w11 = W2s[(k + 1) * DOUT + c2c];
#pragma unroll
        for (int r = 0; r < 4; r++) {
            float2 pk = *(const float2*)(&buf[warp][r][k]);
            a0[r] = fmaf(pk.x, w00, a0[r]);
            a1[r] = fmaf(pk.x, w01, a1[r]);
            a0[r] = fmaf(pk.y, w10, a0[r]);
            a1[r] = fmaf(pk.y, w11, a1[r]);
        }
    }

#pragma unroll
    for (int r = 0; r < 4; r++) {
        int row = row0 + r;
        if (row >= n) break;
        float s = g_dinv[row]; s *= s;
        size_t oo = (size_t)row * DOUT;
        g_hw[oo + lane] = a0[r];
        out [oo + lane] = fmaf(s, a0[r], b2[lane]);
        if (has2) {
            g_hw[oo + c2] = a1[r];
            out [oo + c2] = fmaf(s, a1[r], b2[c2]);
        }
    }
}

// ---------------------------------------------------------------------------
// Layer-2 aggregation of g_hw (34-wide) into out. Half-warp streams, unroll-4.
__global__ void k_agg2(float* __restrict__ out, int n) {
    int warp = threadIdx.x >> 5, lane = threadIdx.x & 31;
    int node = blockIdx.x * 8 + warp;
    if (node >= n) return;
    int beg = g_off[node], end = g_off[node + 1];
    int half = lane >> 4, sub = lane & 15;

    float2 acc  = make_float2(0.f, 0.f);   // features sub*2, sub*2+1
    float2 accx = make_float2(0.f, 0.f);   // features 32,33 (sub==0 lanes)
    for (int j = beg; j < end; j += 32) {
        int idx = j + lane;
        int2 ed = make_int2(0, 0);
        if (idx < end) ed = __ldg(&g_edge[idx]);
        int m  = min(32, end - j);
        int mt = (m + 1) >> 1;
        int t  = 0;
        for (; t + 4 <= mt; t += 4) {
#pragma unroll
            for (int u = 0; u < 4; u++) {
                int l = 2 * (t + u) + half;
                int   s = __shfl_sync(0xffffffffu, ed.x, l);
                float w = __int_as_float(__shfl_sync(0xffffffffu, ed.y, l));
                if (l < m) {
                    const float* hp = g_hw + (size_t)s * DOUT;
                    float2 v = __ldg((const float2*)(hp + sub * 2));
                    acc.x = fmaf(w, v.x, acc.x); acc.y = fmaf(w, v.y, acc.y);
                    if (sub == 0) {
                        float2 uu = __ldg((const float2*)(hp + 32));
                        accx.x = fmaf(w, uu.x, accx.x); accx.y = fmaf(w, uu.y, accx.y);
                    }
                }
            }
        }
        for (; t < mt; t++) {
            int l = 2 * t + half;
            int   s = __shfl_sync(0xffffffffu, ed.x, l);
            float w = __int_as_float(__shfl_sync(0xffffffffu, ed.y, l));
            if (l < m) {
                const float* hp = g_hw + (size_t)s * DOUT;
                float2 v = __ldg((const float2*)(hp + sub * 2));
                acc.x = fmaf(w, v.x, acc.x); acc.y = fmaf(w, v.y, acc.y);
                if (sub == 0) {
                    float2 uu = __ldg((const float2*)(hp + 32));
                    accx.x = fmaf(w, uu.x, accx.x); accx.y = fmaf(w, uu.y, accx.y);
                }
            }
        }
    }
    acc.x  += __shfl_xor_sync(0xffffffffu, acc.x,  16);
    acc.y  += __shfl_xor_sync(0xffffffffu, acc.y,  16);
    accx.x += __shfl_xor_sync(0xffffffffu, accx.x, 16);
    accx.y += __shfl_xor_sync(0xffffffffu, accx.y, 16);
    if (half == 0) {
        float dn = g_dinv[node];
        size_t oo = (size_t)node * DOUT;
        out[oo + sub * 2]     = fmaf(dn, acc.x, out[oo + sub * 2]);
        out[oo + sub * 2 + 1] = fmaf(dn, acc.y, out[oo + sub * 2 + 1]);
        if (sub == 0) {
            out[oo + 32] = fmaf(dn, accx.x, out[oo + 32]);
            out[oo + 33] = fmaf(dn, accx.y, out[oo + 33]);
        }
    }
}

// ---------------------------------------------------------------------------
extern "C" void kernel_launch(void* const* d_in, const int* in_sizes, int n_in,
                              void* d_out, int out_size) {
    const float* x  = (const float*)d_in[0];
    const int*   ei = (const int*)  d_in[1];
    const float* W1 = (const float*)d_in[2];
    const float* b1 = (const float*)d_in[3];
    const float* W2 = (const float*)d_in[4];
    const float* b2 = (const float*)d_in[5];

    int n = in_sizes[0] / DIN;
    int e = in_sizes[1] / 2;
    const int* src = ei;
    const int* dst = ei + e;
    float* out = (float*)d_out;

    int nb = (n + SCAN_BS - 1) / SCAN_BS;

    void* degAddr = 0;
    cudaGetSymbolAddress(&degAddr, g_deg);
    cudaMemsetAsync(degAddr, 0, (size_t)n * sizeof(int));

    k_deg_count<<<(e + 255) / 256, 256>>>(dst, e);
    k_scan1<<<nb, SCAN_BS>>>(n);
    k_scan3<<<nb, SCAN_BS>>>(nb, n);
    k_fill <<<(e + 255) / 256, 256>>>(src, dst, e);

    k_aggx <<<(n + 7) / 8, 256>>>(x, n);
    k_fused<<<(n + 31) / 32, 256>>>(W1, b1, W2, b2, out, n);
    k_agg2 <<<(n + 7) / 8, 256>>>(out, n);
}

// round 5
// speedup vs baseline: 1.4884x; 1.4884x over previous
#include <cuda_runtime.h>

#define N_MAX 100000
#define E_MAX 1200000
#define DIN   64
#define DHID  64
#define DOUT  34
#define SCAN_BS 512
#define NB_MAX ((N_MAX + SCAN_BS - 1) / SCAN_BS)

// ---- scratch (allocation-free: __device__ globals) ----
__device__ int   g_deg [N_MAX];
__device__ float g_dinv[N_MAX];
__device__ int   g_off [N_MAX + 1];       // CSR offsets (real in-edges per dst)
__device__ int   g_cur [N_MAX];           // fill cursors
__device__ int   g_bsum[NB_MAX];          // scan block sums
__device__ int2  g_edge[E_MAX];           // CSR: (src, bits(dinv[src])) per edge
__device__ float g_s   [(size_t)N_MAX * DIN];   // pre-aggregated + self input
__device__ float g_hw  [(size_t)N_MAX * DOUT];  // softmax(relu(h)) @ W2

// ---------------------------------------------------------------------------
__global__ void k_deg_count(const int* __restrict__ dst, int e) {
    int i = blockIdx.x * blockDim.x + threadIdx.x;
    if (i < e) atomicAdd(&g_deg[dst[i]], 1);
}

// ---- per-segment exclusive scan of deg (real in-edges); also dinv --------
__global__ void k_scan1(int n) {
    __shared__ int sh[SCAN_BS];
    int i = blockIdx.x * SCAN_BS + threadIdx.x;
    int v = (i < n) ? g_deg[i] : 0;
    if (i < n) g_dinv[i] = rsqrtf((float)(v + 1));   // +1 self-loop
    sh[threadIdx.x] = v;
    __syncthreads();
    for (int off = 1; off < SCAN_BS; off <<= 1) {
        int t = (threadIdx.x >= off) ? sh[threadIdx.x - off] : 0;
        __syncthreads();
        sh[threadIdx.x] += t;
        __syncthreads();
    }
    if (i < n) g_off[i] = sh[threadIdx.x] - v;
    if (threadIdx.x == SCAN_BS - 1) g_bsum[blockIdx.x] = sh[threadIdx.x];
}

// ---- finalize offsets: each block self-computes its segment prefix -------
__global__ void k_scan3(int nb, int n) {
    __shared__ int red[SCAN_BS / 32];
    __shared__ int pref;
    int sb = blockIdx.x, t = threadIdx.x;

    int v = (t < sb) ? g_bsum[t] : 0;
#pragma unroll
    for (int o = 16; o; o >>= 1) v += __shfl_xor_sync(0xffffffffu, v, o);
    if ((t & 31) == 0) red[t >> 5] = v;
    __syncthreads();
    if (t < 32) {
        int vv = (t < SCAN_BS / 32) ? red[t] : 0;
#pragma unroll
        for (int o = 16; o; o >>= 1) vv += __shfl_xor_sync(0xffffffffu, vv, o);
        if (t == 0) pref = vv;
    }
    __syncthreads();
    int prefix = pref;

    int i = sb * SCAN_BS + t;
    if (i < n) {
        int o = g_off[i] + prefix;
        g_off[i] = o;
        g_cur[i] = o;
    }
    if (sb == nb - 1 && t == 0) g_off[n] = prefix + g_bsum[sb];
}

__global__ void k_fill(const int* __restrict__ src, const int* __restrict__ dst, int e) {
    int i = blockIdx.x * blockDim.x + threadIdx.x;
    if (i < e) {
        int s = src[i];
        int pos = atomicAdd(&g_cur[dst[i]], 1);
        g_edge[pos] = make_int2(s, __float_as_int(g_dinv[s]));
    }
}

// ---------------------------------------------------------------------------
// Pre-GEMM aggregation: g_s[i] = dinv[i]*(sum_e dinv[src]*x[src] + dinv[i]*x[i])
// Warp per node; two half-warp edge streams (16 lanes x float4 = 256B reads),
// unroll-2 -> 4 loads in flight. (Round-2 proven configuration.)
__global__ void k_aggx(const float* __restrict__ x, int n) {
    int warp = threadIdx.x >> 5, lane = threadIdx.x & 31;
    int node = blockIdx.x * 8 + warp;
    if (node >= n) return;
    int beg = g_off[node], end = g_off[node + 1];
    int half = lane >> 4, sub = lane & 15;

    float4 acc = make_float4(0.f, 0.f, 0.f, 0.f);
    for (int j = beg; j < end; j += 32) {
        int idx = j + lane;
        int2 ed = make_int2(0, 0);
        if (idx < end) ed = g_edge[idx];
        int m  = min(32, end - j);
        int mt = (m + 1) >> 1;       // warp-uniform trip count
        int t  = 0;
        for (; t + 2 <= mt; t += 2) {
            int l0 = 2 * t + half, l1 = l0 + 2;
            int   s0 = __shfl_sync(0xffffffffu, ed.x, l0);
            float w0 = __int_as_float(__shfl_sync(0xffffffffu, ed.y, l0));
            int   s1 = __shfl_sync(0xffffffffu, ed.x, l1);
            float w1 = __int_as_float(__shfl_sync(0xffffffffu, ed.y, l1));
            if (l0 < m) {
                float4 v = *(const float4*)(x + (size_t)s0 * DIN + sub * 4);
                acc.x = fmaf(w0, v.x, acc.x); acc.y = fmaf(w0, v.y, acc.y);
                acc.z = fmaf(w0, v.z, acc.z); acc.w = fmaf(w0, v.w, acc.w);
            }
            if (l1 < m) {
                float4 v = *(const float4*)(x + (size_t)s1 * DIN + sub * 4);
                acc.x = fmaf(w1, v.x, acc.x); acc.y = fmaf(w1, v.y, acc.y);
                acc.z = fmaf(w1, v.z, acc.z); acc.w = fmaf(w1, v.w, acc.w);
            }
        }
        for (; t < mt; t++) {
            int l0 = 2 * t + half;
            int   s0 = __shfl_sync(0xffffffffu, ed.x, l0);
            float w0 = __int_as_float(__shfl_sync(0xffffffffu, ed.y, l0));
            if (l0 < m) {
                float4 v = *(const float4*)(x + (size_t)s0 * DIN + sub * 4);
                acc.x = fmaf(w0, v.x, acc.x); acc.y = fmaf(w0, v.y, acc.y);
                acc.z = fmaf(w0, v.z, acc.z); acc.w = fmaf(w0, v.w, acc.w);
            }
        }
    }
    acc.x += __shfl_xor_sync(0xffffffffu, acc.x, 16);
    acc.y += __shfl_xor_sync(0xffffffffu, acc.y, 16);
    acc.z += __shfl_xor_sync(0xffffffffu, acc.z, 16);
    acc.w += __shfl_xor_sync(0xffffffffu, acc.w, 16);
    if (half == 0) {
        float dn = g_dinv[node];
        float4 xv = *(const float4*)(x + (size_t)node * DIN + sub * 4);
        float4 s;
        s.x = dn * fmaf(dn, xv.x, acc.x);
        s.y = dn * fmaf(dn, xv.y, acc.y);
        s.z = dn * fmaf(dn, xv.z, acc.z);
        s.w = dn * fmaf(dn, xv.w, acc.w);
        *(float4*)(g_s + (size_t)node * DIN + sub * 4) = s;
    }
}

// ---------------------------------------------------------------------------
// Fused: h = g_s @ W1 + b1 ; p = softmax(relu(h)) ; hw = p @ W2 ;
// out init = b2 + dinv^2 * hw. Warp handles 4 rows; 2 cols/lane tile.
// (Round-2 proven configuration.)
__global__ void k_fused(const float* __restrict__ W1, const float* __restrict__ b1,
                        const float* __restrict__ W2, const float* __restrict__ b2,
                        float* __restrict__ out, int n) {
    __shared__ float W1s[DIN * DHID];       // 16 KB
    __shared__ float W2s[DHID * DOUT];      // 8.5 KB
    __shared__ float buf[8][4][DHID];       // 8 KB: xs then ps
    for (int i = threadIdx.x; i < DIN * DHID; i += blockDim.x)  W1s[i] = W1[i];
    for (int i = threadIdx.x; i < DHID * DOUT; i += blockDim.x) W2s[i] = W2[i];
    __syncthreads();

    int warp = threadIdx.x >> 5, lane = threadIdx.x & 31;
    int row0 = blockIdx.x * 32 + warp * 4;

#pragma unroll
    for (int r = 0; r < 4; r++) {
        int row = row0 + r;
        float2 xv = make_float2(0.f, 0.f);
        if (row < n) xv = *(const float2*)(g_s + (size_t)row * DIN + lane * 2);
        buf[warp][r][lane * 2]     = xv.x;
        buf[warp][r][lane * 2 + 1] = xv.y;
    }
    __syncwarp();

    float2 a[4];
#pragma unroll
    for (int r = 0; r < 4; r++) a[r] = make_float2(0.f, 0.f);
#pragma unroll
    for (int k = 0; k < DIN; k++) {
        float2 w = *(const float2*)(W1s + k * DHID + lane * 2);
#pragma unroll
        for (int r = 0; r < 4; r++) {
            float xk = buf[warp][r][k];
            a[r].x = fmaf(xk, w.x, a[r].x);
            a[r].y = fmaf(xk, w.y, a[r].y);
        }
    }
    __syncwarp();

    float2 bb = *(const float2*)(b1 + lane * 2);
#pragma unroll
    for (int r = 0; r < 4; r++) {
        float v0 = fmaxf(a[r].x + bb.x, 0.f);
        float v1 = fmaxf(a[r].y + bb.y, 0.f);
        float m = fmaxf(v0, v1);
#pragma unroll
        for (int off = 16; off; off >>= 1)
            m = fmaxf(m, __shfl_xor_sync(0xffffffffu, m, off));
        float e0 = __expf(v0 - m), e1 = __expf(v1 - m);
        float ssum = e0 + e1;
#pragma unroll
        for (int off = 16; off; off >>= 1)
            ssum += __shfl_xor_sync(0xffffffffu, ssum, off);
        float inv = 1.0f / ssum;
        buf[warp][r][lane * 2]     = e0 * inv;
        buf[warp][r][lane * 2 + 1] = e1 * inv;
    }
    __syncwarp();

    int  c2   = lane + 32;
    bool has2 = (c2 < DOUT);
    int  c2c  = has2 ? c2 : (DOUT - 1);
    float a0[4] = {0.f, 0.f, 0.f, 0.f};
    float a1[4] = {0.f, 0.f, 0.f, 0.f};
#pragma unroll
    for (int k = 0; k < DHID; k++) {
        float w0 = W2s[k * DOUT + lane];
        float w1 = W2s[k * DOUT + c2c];
#pragma unroll
        for (int r = 0; r < 4; r++) {
            float pk = buf[warp][r][k];
            a0[r] = fmaf(pk, w0, a0[r]);
            a1[r] = fmaf(pk, w1, a1[r]);
        }
    }

#pragma unroll
    for (int r = 0; r < 4; r++) {
        int row = row0 + r;
        if (row >= n) break;
        float s = g_dinv[row]; s *= s;
        size_t oo = (size_t)row * DOUT;
        g_hw[oo + lane] = a0[r];
        out [oo + lane] = fmaf(s, a0[r], b2[lane]);
        if (has2) {
            g_hw[oo + c2] = a1[r];
            out [oo + c2] = fmaf(s, a1[r], b2[c2]);
        }
    }
}

// ---------------------------------------------------------------------------
// Layer-2 aggregation of g_hw (34-wide) into out. Half-warp streams, unroll-2.
// (Round-2 proven configuration.)
__global__ void k_agg2(float* __restrict__ out, int n) {
    int warp = threadIdx.x >> 5, lane = threadIdx.x & 31;
    int node = blockIdx.x * 8 + warp;
    if (node >= n) return;
    int beg = g_off[node], end = g_off[node + 1];
    int half = lane >> 4, sub = lane & 15;

    float2 acc  = make_float2(0.f, 0.f);   // features sub*2, sub*2+1
    float2 accx = make_float2(0.f, 0.f);   // features 32,33 (sub==0 lanes)
    for (int j = beg; j < end; j += 32) {
        int idx = j + lane;
        int2 ed = make_int2(0, 0);
        if (idx < end) ed = g_edge[idx];
        int m  = min(32, end - j);
        int mt = (m + 1) >> 1;
        int t  = 0;
        for (; t + 2 <= mt; t += 2) {
            int l0 = 2 * t + half, l1 = l0 + 2;
            int   s0 = __shfl_sync(0xffffffffu, ed.x, l0);
            float w0 = __int_as_float(__shfl_sync(0xffffffffu, ed.y, l0));
            int   s1 = __shfl_sync(0xffffffffu, ed.x, l1);
            float w1 = __int_as_float(__shfl_sync(0xffffffffu, ed.y, l1));
            if (l0 < m) {
                const float* hp = g_hw + (size_t)s0 * DOUT;
                float2 v = *(const float2*)(hp + sub * 2);
                acc.x = fmaf(w0, v.x, acc.x); acc.y = fmaf(w0, v.y, acc.y);
                if (sub == 0) {
                    float2 u = *(const float2*)(hp + 32);
                    accx.x = fmaf(w0, u.x, accx.x); accx.y = fmaf(w0, u.y, accx.y);
                }
            }
            if (l1 < m) {
                const float* hp = g_hw + (size_t)s1 * DOUT;
                float2 v = *(const float2*)(hp + sub * 2);
                acc.x = fmaf(w1, v.x, acc.x); acc.y = fmaf(w1, v.y, acc.y);
                if (sub == 0) {
                    float2 u = *(const float2*)(hp + 32);
                    accx.x = fmaf(w1, u.x, accx.x); accx.y = fmaf(w1, u.y, accx.y);
                }
            }
        }
        for (; t < mt; t++) {
            int l0 = 2 * t + half;
            int   s0 = __shfl_sync(0xffffffffu, ed.x, l0);
            float w0 = __int_as_float(__shfl_sync(0xffffffffu, ed.y, l0));
            if (l0 < m) {
                const float* hp = g_hw + (size_t)s0 * DOUT;
                float2 v = *(const float2*)(hp + sub * 2);
                acc.x = fmaf(w0, v.x, acc.x); acc.y = fmaf(w0, v.y, acc.y);
                if (sub == 0) {
                    float2 u = *(const float2*)(hp + 32);
                    accx.x = fmaf(w0, u.x, accx.x); accx.y = fmaf(w0, u.y, accx.y);
                }
            }
        }
    }
    acc.x  += __shfl_xor_sync(0xffffffffu, acc.x,  16);
    acc.y  += __shfl_xor_sync(0xffffffffu, acc.y,  16);
    accx.x += __shfl_xor_sync(0xffffffffu, accx.x, 16);
    accx.y += __shfl_xor_sync(0xffffffffu, accx.y, 16);
    if (half == 0) {
        float dn = g_dinv[node];
        size_t oo = (size_t)node * DOUT;
        out[oo + sub * 2]     = fmaf(dn, acc.x, out[oo + sub * 2]);
        out[oo + sub * 2 + 1] = fmaf(dn, acc.y, out[oo + sub * 2 + 1]);
        if (sub == 0) {
            out[oo + 32] = fmaf(dn, accx.x, out[oo + 32]);
            out[oo + 33] = fmaf(dn, accx.y, out[oo + 33]);
        }
    }
}

// ---------------------------------------------------------------------------
extern "C" void kernel_launch(void* const* d_in, const int* in_sizes, int n_in,
                              void* d_out, int out_size) {
    const float* x  = (const float*)d_in[0];
    const int*   ei = (const int*)  d_in[1];
    const float* W1 = (const float*)d_in[2];
    const float* b1 = (const float*)d_in[3];
    const float* W2 = (const float*)d_in[4];
    const float* b2 = (const float*)d_in[5];

    int n = in_sizes[0] / DIN;
    int e = in_sizes[1] / 2;
    const int* src = ei;
    const int* dst = ei + e;
    float* out = (float*)d_out;

    int nb = (n + SCAN_BS - 1) / SCAN_BS;

    void* degAddr = 0;
    cudaGetSymbolAddress(&degAddr, g_deg);
    cudaMemsetAsync(degAddr, 0, (size_t)n * sizeof(int));

    k_deg_count<<<(e + 255) / 256, 256>>>(dst, e);
    k_scan1<<<nb, SCAN_BS>>>(n);
    k_scan3<<<nb, SCAN_BS>>>(nb, n);
    k_fill <<<(e + 255) / 256, 256>>>(src, dst, e);

    k_aggx <<<(n + 7) / 8, 256>>>(x, n);
    k_fused<<<(n + 31) / 32, 256>>>(W1, b1, W2, b2, out, n);
    k_agg2 <<<(n + 7) / 8, 256>>>(out, n);
}

// round 6
// speedup vs baseline: 1.5241x; 1.0240x over previous
#include <cuda_runtime.h>
#include <cuda_fp16.h>

#define N_MAX 100000
#define E_MAX 1200000
#define DIN   64
#define DHID  64
#define DOUT  34
#define SCAN_BS 512
#define NB_MAX ((N_MAX + SCAN_BS - 1) / SCAN_BS)

// ---- scratch (allocation-free: __device__ globals) ----
__device__ int    g_deg [N_MAX];
__device__ float  g_dinv[N_MAX];
__device__ int    g_off [N_MAX + 1];      // CSR offsets (real in-edges per dst)
__device__ int    g_cur [N_MAX];          // fill cursors
__device__ int    g_bsum[NB_MAX];         // scan block sums
__device__ int    g_esrc[E_MAX];          // CSR: src per bucketed edge
__device__ __half g_xh [(size_t)N_MAX * DIN];   // dinv[i]*x[i] in fp16
__device__ float  g_s  [(size_t)N_MAX * DIN];   // pre-aggregated + self input
__device__ __half g_hwh[(size_t)N_MAX * DOUT];  // dinv[i]*hw[i] in fp16

// ---------------------------------------------------------------------------
__global__ void k_deg_count(const int* __restrict__ dst, int e) {
    int i0 = (blockIdx.x * blockDim.x + threadIdx.x) * 4;
    if (i0 + 3 < e) {
        int d0 = dst[i0], d1 = dst[i0 + 1], d2 = dst[i0 + 2], d3 = dst[i0 + 3];
        atomicAdd(&g_deg[d0], 1);
        atomicAdd(&g_deg[d1], 1);
        atomicAdd(&g_deg[d2], 1);
        atomicAdd(&g_deg[d3], 1);
    } else {
        for (int i = i0; i < e; i++) atomicAdd(&g_deg[dst[i]], 1);
    }
}

// ---- per-segment exclusive scan of deg (real in-edges); also dinv --------
__global__ void k_scan1(int n) {
    __shared__ int sh[SCAN_BS];
    int i = blockIdx.x * SCAN_BS + threadIdx.x;
    int v = (i < n) ? g_deg[i] : 0;
    if (i < n) g_dinv[i] = rsqrtf((float)(v + 1));   // +1 self-loop
    sh[threadIdx.x] = v;
    __syncthreads();
    for (int off = 1; off < SCAN_BS; off <<= 1) {
        int t = (threadIdx.x >= off) ? sh[threadIdx.x - off] : 0;
        __syncthreads();
        sh[threadIdx.x] += t;
        __syncthreads();
    }
    if (i < n) g_off[i] = sh[threadIdx.x] - v;
    if (threadIdx.x == SCAN_BS - 1) g_bsum[blockIdx.x] = sh[threadIdx.x];
}

// ---- finalize offsets: each block self-computes its segment prefix -------
__global__ void k_scan3(int nb, int n) {
    __shared__ int red[SCAN_BS / 32];
    __shared__ int pref;
    int sb = blockIdx.x, t = threadIdx.x;

    int v = (t < sb) ? g_bsum[t] : 0;
#pragma unroll
    for (int o = 16; o; o >>= 1) v += __shfl_xor_sync(0xffffffffu, v, o);
    if ((t & 31) == 0) red[t >> 5] = v;
    __syncthreads();
    if (t < 32) {
        int vv = (t < SCAN_BS / 32) ? red[t] : 0;
#pragma unroll
        for (int o = 16; o; o >>= 1) vv += __shfl_xor_sync(0xffffffffu, vv, o);
        if (t == 0) pref = vv;
    }
    __syncthreads();
    int prefix = pref;

    int i = sb * SCAN_BS + t;
    if (i < n) {
        int o = g_off[i] + prefix;
        g_off[i] = o;
        g_cur[i] = o;
    }
    if (sb == nb - 1 && t == 0) g_off[n] = prefix + g_bsum[sb];
}

// ---- convert x to fp16, pre-scaled by dinv: g_xh[i] = half(dinv[i]*x[i]) --
__global__ void k_x2h(const float* __restrict__ x, int n) {
    int tid = blockIdx.x * blockDim.x + threadIdx.x;
    int row = tid >> 4, sub = tid & 15;
    if (row >= n) return;
    float dn = g_dinv[row];
    float4 v = *(const float4*)(x + (size_t)row * DIN + sub * 4);
    __half2 h01 = __floats2half2_rn(v.x * dn, v.y * dn);
    __half2 h23 = __floats2half2_rn(v.z * dn, v.w * dn);
    uint2 raw;
    raw.x = *(unsigned*)&h01;
    raw.y = *(unsigned*)&h23;
    *(uint2*)(g_xh + (size_t)row * DIN + sub * 4) = raw;
}

// ---- CSR fill: 4 edges/thread for atomic MLP -----------------------------
__global__ void k_fill(const int* __restrict__ src, const int* __restrict__ dst, int e) {
    int i0 = (blockIdx.x * blockDim.x + threadIdx.x) * 4;
    if (i0 + 3 < e) {
        int s0 = src[i0], s1 = src[i0 + 1], s2 = src[i0 + 2], s3 = src[i0 + 3];
        int d0 = dst[i0], d1 = dst[i0 + 1], d2 = dst[i0 + 2], d3 = dst[i0 + 3];
        int p0 = atomicAdd(&g_cur[d0], 1);
        int p1 = atomicAdd(&g_cur[d1], 1);
        int p2 = atomicAdd(&g_cur[d2], 1);
        int p3 = atomicAdd(&g_cur[d3], 1);
        g_esrc[p0] = s0; g_esrc[p1] = s1; g_esrc[p2] = s2; g_esrc[p3] = s3;
    } else {
        for (int i = i0; i < e; i++) {
            int pos = atomicAdd(&g_cur[dst[i]], 1);
            g_esrc[pos] = src[i];
        }
    }
}

// ---------------------------------------------------------------------------
// Pre-GEMM aggregation: g_s[i] = dinv[i]*(sum_e x'[src] ) + dinv[i]^2*x[i]
// where x' = dinv*x (fp16, pre-scaled). Unweighted sum — no per-edge weight.
// Warp per node; two half-warp edge streams (16 lanes x 8B = 128B rows),
// unroll-2 (proven configuration).
__global__ void k_aggx(const float* __restrict__ x, int n) {
    int warp = threadIdx.x >> 5, lane = threadIdx.x & 31;
    int node = blockIdx.x * 8 + warp;
    if (node >= n) return;
    int beg = g_off[node], end = g_off[node + 1];
    int half = lane >> 4, sub = lane & 15;

    float4 acc = make_float4(0.f, 0.f, 0.f, 0.f);
    for (int j = beg; j < end; j += 32) {
        int idx = j + lane;
        int ed = (idx < end) ? g_esrc[idx] : 0;
        int m  = min(32, end - j);
        int mt = (m + 1) >> 1;       // warp-uniform trips per half-stream
        int t  = 0;
        for (; t + 2 <= mt; t += 2) {
            int l0 = 2 * t + half, l1 = l0 + 2;
            int s0 = __shfl_sync(0xffffffffu, ed, l0);
            int s1 = __shfl_sync(0xffffffffu, ed, l1);
            if (l0 < m) {
                uint2 raw = *(const uint2*)(g_xh + (size_t)s0 * DIN + sub * 4);
                float2 f0 = __half22float2(*(__half2*)&raw.x);
                float2 f1 = __half22float2(*(__half2*)&raw.y);
                acc.x += f0.x; acc.y += f0.y; acc.z += f1.x; acc.w += f1.y;
            }
            if (l1 < m) {
                uint2 raw = *(const uint2*)(g_xh + (size_t)s1 * DIN + sub * 4);
                float2 f0 = __half22float2(*(__half2*)&raw.x);
                float2 f1 = __half22float2(*(__half2*)&raw.y);
                acc.x += f0.x; acc.y += f0.y; acc.z += f1.x; acc.w += f1.y;
            }
        }
        for (; t < mt; t++) {
            int l0 = 2 * t + half;
            int s0 = __shfl_sync(0xffffffffu, ed, l0);
            if (l0 < m) {
                uint2 raw = *(const uint2*)(g_xh + (size_t)s0 * DIN + sub * 4);
                float2 f0 = __half22float2(*(__half2*)&raw.x);
                float2 f1 = __half22float2(*(__half2*)&raw.y);
                acc.x += f0.x; acc.y += f0.y; acc.z += f1.x; acc.w += f1.y;
            }
        }
    }
    acc.x += __shfl_xor_sync(0xffffffffu, acc.x, 16);
    acc.y += __shfl_xor_sync(0xffffffffu, acc.y, 16);
    acc.z += __shfl_xor_sync(0xffffffffu, acc.z, 16);
    acc.w += __shfl_xor_sync(0xffffffffu, acc.w, 16);
    if (half == 0) {
        float dn = g_dinv[node];
        float4 xv = *(const float4*)(x + (size_t)node * DIN + sub * 4);  // fp32 self term
        float4 s;
        s.x = fmaf(dn, acc.x, dn * dn * xv.x);
        s.y = fmaf(dn, acc.y, dn * dn * xv.y);
        s.z = fmaf(dn, acc.z, dn * dn * xv.z);
        s.w = fmaf(dn, acc.w, dn * dn * xv.w);
        *(float4*)(g_s + (size_t)node * DIN + sub * 4) = s;
    }
}

// ---------------------------------------------------------------------------
// Fused: h = g_s @ W1 + b1 ; p = softmax(relu(h)) ; hw = p @ W2 ;
// out init = b2 + dinv^2 * hw ; g_hwh = half(dinv * hw).
__global__ void k_fused(const float* __restrict__ W1, const float* __restrict__ b1,
                        const float* __restrict__ W2, const float* __restrict__ b2,
                        float* __restrict__ out, int n) {
    __shared__ float W1s[DIN * DHID];       // 16 KB
    __shared__ float W2s[DHID * DOUT];      // 8.5 KB
    __shared__ float buf[8][4][DHID];       // 8 KB: xs then ps
    for (int i = threadIdx.x; i < DIN * DHID; i += blockDim.x)  W1s[i] = W1[i];
    for (int i = threadIdx.x; i < DHID * DOUT; i += blockDim.x) W2s[i] = W2[i];
    __syncthreads();

    int warp = threadIdx.x >> 5, lane = threadIdx.x & 31;
    int row0 = blockIdx.x * 32 + warp * 4;

#pragma unroll
    for (int r = 0; r < 4; r++) {
        int row = row0 + r;
        float2 xv = make_float2(0.f, 0.f);
        if (row < n) xv = *(const float2*)(g_s + (size_t)row * DIN + lane * 2);
        buf[warp][r][lane * 2]     = xv.x;
        buf[warp][r][lane * 2 + 1] = xv.y;
    }
    __syncwarp();

    float2 a[4];
#pragma unroll
    for (int r = 0; r < 4; r++) a[r] = make_float2(0.f, 0.f);
#pragma unroll
    for (int k = 0; k < DIN; k++) {
        float2 w = *(const float2*)(W1s + k * DHID + lane * 2);
#pragma unroll
        for (int r = 0; r < 4; r++) {
            float xk = buf[warp][r][k];
            a[r].x = fmaf(xk, w.x, a[r].x);
            a[r].y = fmaf(xk, w.y, a[r].y);
        }
    }
    __syncwarp();

    float2 bb = *(const float2*)(b1 + lane * 2);
#pragma unroll
    for (int r = 0; r < 4; r++) {
        float v0 = fmaxf(a[r].x + bb.x, 0.f);
        float v1 = fmaxf(a[r].y + bb.y, 0.f);
        float m = fmaxf(v0, v1);
#pragma unroll
        for (int off = 16; off; off >>= 1)
            m = fmaxf(m, __shfl_xor_sync(0xffffffffu, m, off));
        float e0 = __expf(v0 - m), e1 = __expf(v1 - m);
        float ssum = e0 + e1;
#pragma unroll
        for (int off = 16; off; off >>= 1)
            ssum += __shfl_xor_sync(0xffffffffu, ssum, off);
        float inv = 1.0f / ssum;
        buf[warp][r][lane * 2]     = e0 * inv;
        buf[warp][r][lane * 2 + 1] = e1 * inv;
    }
    __syncwarp();

    int  c2   = lane + 32;
    bool has2 = (c2 < DOUT);
    int  c2c  = has2 ? c2 : (DOUT - 1);
    float a0[4] = {0.f, 0.f, 0.f, 0.f};
    float a1[4] = {0.f, 0.f, 0.f, 0.f};
#pragma unroll
    for (int k = 0; k < DHID; k++) {
        float w0 = W2s[k * DOUT + lane];
        float w1 = W2s[k * DOUT + c2c];
#pragma unroll
        for (int r = 0; r < 4; r++) {
            float pk = buf[warp][r][k];
            a0[r] = fmaf(pk, w0, a0[r]);
            a1[r] = fmaf(pk, w1, a1[r]);
        }
    }

#pragma unroll
    for (int r = 0; r < 4; r++) {
        int row = row0 + r;
        if (row >= n) break;
        float dn = g_dinv[row];
        float s = dn * dn;
        size_t oo = (size_t)row * DOUT;
        g_hwh[oo + lane] = __float2half(dn * a0[r]);
        out  [oo + lane] = fmaf(s, a0[r], b2[lane]);
        if (has2) {
            g_hwh[oo + c2] = __float2half(dn * a1[r]);
            out  [oo + c2] = fmaf(s, a1[r], b2[c2]);
        }
    }
}

// ---------------------------------------------------------------------------
// Layer-2 aggregation of g_hwh (34 halves/row, pre-scaled by dinv) into out.
// Unweighted sum; half-warp streams, unroll-2 (proven configuration).
__global__ void k_agg2(float* __restrict__ out, int n) {
    int warp = threadIdx.x >> 5, lane = threadIdx.x & 31;
    int node = blockIdx.x * 8 + warp;
    if (node >= n) return;
    int beg = g_off[node], end = g_off[node + 1];
    int half = lane >> 4, sub = lane & 15;

    float2 acc  = make_float2(0.f, 0.f);   // features sub*2, sub*2+1
    float2 accx = make_float2(0.f, 0.f);   // features 32,33 (sub==0 lanes)
    for (int j = beg; j < end; j += 32) {
        int idx = j + lane;
        int ed = (idx < end) ? g_esrc[idx] : 0;
        int m  = min(32, end - j);
        int mt = (m + 1) >> 1;
        int t  = 0;
        for (; t + 2 <= mt; t += 2) {
            int l0 = 2 * t + half, l1 = l0 + 2;
            int s0 = __shfl_sync(0xffffffffu, ed, l0);
            int s1 = __shfl_sync(0xffffffffu, ed, l1);
            if (l0 < m) {
                const __half* hp = g_hwh + (size_t)s0 * DOUT;
                float2 v = __half22float2(*(const __half2*)(hp + sub * 2));
                acc.x += v.x; acc.y += v.y;
                if (sub == 0) {
                    float2 u = __half22float2(*(const __half2*)(hp + 32));
                    accx.x += u.x; accx.y += u.y;
                }
            }
            if (l1 < m) {
                const __half* hp = g_hwh + (size_t)s1 * DOUT;
                float2 v = __half22float2(*(const __half2*)(hp + sub * 2));
                acc.x += v.x; acc.y += v.y;
                if (sub == 0) {
                    float2 u = __half22float2(*(const __half2*)(hp + 32));
                    accx.x += u.x; accx.y += u.y;
                }
            }
        }
        for (; t < mt; t++) {
            int l0 = 2 * t + half;
            int s0 = __shfl_sync(0xffffffffu, ed, l0);
            if (l0 < m) {
                const __half* hp = g_hwh + (size_t)s0 * DOUT;
                float2 v = __half22float2(*(const __half2*)(hp + sub * 2));
                acc.x += v.x; acc.y += v.y;
                if (sub == 0) {
                    float2 u = __half22float2(*(const __half2*)(hp + 32));
                    accx.x += u.x; accx.y += u.y;
                }
            }
        }
    }
    acc.x  += __shfl_xor_sync(0xffffffffu, acc.x,  16);
    acc.y  += __shfl_xor_sync(0xffffffffu, acc.y,  16);
    accx.x += __shfl_xor_sync(0xffffffffu, accx.x, 16);
    accx.y += __shfl_xor_sync(0xffffffffu, accx.y, 16);
    if (half == 0) {
        float dn = g_dinv[node];
        size_t oo = (size_t)node * DOUT;
        out[oo + sub * 2]     = fmaf(dn, acc.x, out[oo + sub * 2]);
        out[oo + sub * 2 + 1] = fmaf(dn, acc.y, out[oo + sub * 2 + 1]);
        if (sub == 0) {
            out[oo + 32] = fmaf(dn, accx.x, out[oo + 32]);
            out[oo + 33] = fmaf(dn, accx.y, out[oo + 33]);
        }
    }
}

// ---------------------------------------------------------------------------
extern "C" void kernel_launch(void* const* d_in, const int* in_sizes, int n_in,
                              void* d_out, int out_size) {
    const float* x  = (const float*)d_in[0];
    const int*   ei = (const int*)  d_in[1];
    const float* W1 = (const float*)d_in[2];
    const float* b1 = (const float*)d_in[3];
    const float* W2 = (const float*)d_in[4];
    const float* b2 = (const float*)d_in[5];

    int n = in_sizes[0] / DIN;
    int e = in_sizes[1] / 2;
    const int* src = ei;
    const int* dst = ei + e;
    float* out = (float*)d_out;

    int nb = (n + SCAN_BS - 1) / SCAN_BS;
    int e4 = (e + 3) / 4;

    void* degAddr = 0;
    cudaGetSymbolAddress(&degAddr, g_deg);
    cudaMemsetAsync(degAddr, 0, (size_t)n * sizeof(int));

    k_deg_count<<<(e4 + 255) / 256, 256>>>(dst, e);
    k_scan1<<<nb, SCAN_BS>>>(n);
    k_scan3<<<nb, SCAN_BS>>>(nb, n);
    k_x2h  <<<(n * 16 + 255) / 256, 256>>>(x, n);
    k_fill <<<(e4 + 255) / 256, 256>>>(src, dst, e);

    k_aggx <<<(n + 7) / 8, 256>>>(x, n);
    k_fused<<<(n + 31) / 32, 256>>>(W1, b1, W2, b2, out, n);
    k_agg2 <<<(n + 7) / 8, 256>>>(out, n);
}